// round 12
// baseline (speedup 1.0000x reference)
#include <cuda_runtime.h>
#include <cuda_bf16.h>
#include <math.h>

// RankingLoss: B=65536 rows, C=1024 classes, float32 scores, int32 labels.
// loss = mean_b [ log1p(exp(2*(2.5 - s_pos))) + log1p(exp(2*(0.5 + s_neg))) ]
// Two consecutive rows per warp, statically addressed (+256 float4 offset),
// hand-scheduled so row1's loads are in flight through row0's reduction and
// epilogue — no per-warp load-silent window, no loop-carried pointers.

#define NUM_B 65536
#define NUM_C 1024
#define WARPS_PER_BLOCK 8
#define ROW_F4 (NUM_C / 4)    // 256 float4 per row

__device__ double g_acc = 0.0;
__device__ unsigned int g_done = 0;

__device__ __forceinline__ float softplus_g(float t) {
    return (t > 20.0f) ? t : log1pf(__expf(t));
}

__device__ __forceinline__ void consume_f4(float4 v, int f4, int lblf4,
                                           int lblsub, float& vmax, float& spos) {
    float a0 = v.x, a1 = v.y, a2 = v.z, a3 = v.w;
    if (f4 == lblf4) {
        if (lblsub == 0) { spos = a0; a0 = -INFINITY; }
        else if (lblsub == 1) { spos = a1; a1 = -INFINITY; }
        else if (lblsub == 2) { spos = a2; a2 = -INFINITY; }
        else                  { spos = a3; a3 = -INFINITY; }
    }
    vmax = fmaxf(vmax, fmaxf(fmaxf(a0, a1), fmaxf(a2, a3)));
}

// (256, 6): pins regs <= 42 -> 48 warps/SM resident.
__global__ void __launch_bounds__(WARPS_PER_BLOCK * 32, 6)
ranking_loss_kernel(const float* __restrict__ scores,
                    const int* __restrict__ labels,
                    float* __restrict__ out)
{
    const int lane  = threadIdx.x & 31;
    const int warp  = threadIdx.x >> 5;
    const int gwarp = blockIdx.x * WARPS_PER_BLOCK + warp;
    const int row0  = gwarp * 2;               // rows row0, row0+1

    const int2 lblp   = *(const int2*)(labels + row0);
    const int lbl0    = lblp.x,      lbl1    = lblp.y;
    const int lblf4_0 = lbl0 >> 2,   lblf4_1 = lbl1 >> 2;
    const int lblsub0 = lbl0 & 3,    lblsub1 = lbl1 & 3;

    const float4* __restrict__ rp =
        (const float4*)(scores + (size_t)row0 * NUM_C);

    float vmax0 = -INFINITY, spos0 = -INFINITY;
    float vmax1 = -INFINITY, spos1 = -INFINITY;

    // ---- row0 batch0 + batch1 issued (MLP=8 burst) ----
    float4 a0 = rp[0 * 32 + lane];
    float4 a1 = rp[1 * 32 + lane];
    float4 a2 = rp[2 * 32 + lane];
    float4 a3 = rp[3 * 32 + lane];
    float4 b0 = rp[4 * 32 + lane];
    float4 b1 = rp[5 * 32 + lane];
    float4 b2 = rp[6 * 32 + lane];
    float4 b3 = rp[7 * 32 + lane];

    // consume row0 batch0
    consume_f4(a0, 0 * 32 + lane, lblf4_0, lblsub0, vmax0, spos0);
    consume_f4(a1, 1 * 32 + lane, lblf4_0, lblsub0, vmax0, spos0);
    consume_f4(a2, 2 * 32 + lane, lblf4_0, lblsub0, vmax0, spos0);
    consume_f4(a3, 3 * 32 + lane, lblf4_0, lblsub0, vmax0, spos0);

    // issue row1 batch0 into the regs just freed (static +ROW_F4 offset)
    a0 = rp[ROW_F4 + 0 * 32 + lane];
    a1 = rp[ROW_F4 + 1 * 32 + lane];
    a2 = rp[ROW_F4 + 2 * 32 + lane];
    a3 = rp[ROW_F4 + 3 * 32 + lane];

    // consume row0 batch1
    consume_f4(b0, 4 * 32 + lane, lblf4_0, lblsub0, vmax0, spos0);
    consume_f4(b1, 5 * 32 + lane, lblf4_0, lblsub0, vmax0, spos0);
    consume_f4(b2, 6 * 32 + lane, lblf4_0, lblsub0, vmax0, spos0);
    consume_f4(b3, 7 * 32 + lane, lblf4_0, lblsub0, vmax0, spos0);

    // issue row1 batch1 — now row1 fully in flight
    b0 = rp[ROW_F4 + 4 * 32 + lane];
    b1 = rp[ROW_F4 + 5 * 32 + lane];
    b2 = rp[ROW_F4 + 6 * 32 + lane];
    b3 = rp[ROW_F4 + 7 * 32 + lane];

    // ---- row0 reduction while row1 loads are outstanding ----
    #pragma unroll
    for (int o = 16; o > 0; o >>= 1)
        vmax0 = fmaxf(vmax0, __shfl_xor_sync(0xffffffffu, vmax0, o));
    spos0 = __shfl_sync(0xffffffffu, spos0, lblf4_0 & 31);

    // consume row1 batch0
    consume_f4(a0, 0 * 32 + lane, lblf4_1, lblsub1, vmax1, spos1);
    consume_f4(a1, 1 * 32 + lane, lblf4_1, lblsub1, vmax1, spos1);
    consume_f4(a2, 2 * 32 + lane, lblf4_1, lblsub1, vmax1, spos1);
    consume_f4(a3, 3 * 32 + lane, lblf4_1, lblsub1, vmax1, spos1);

    // row0 epilogue overlapped with row1 batch1 in flight
    float warp_loss = 0.0f;
    if (lane == 0) {
        const float s_neg0 = (lbl0 == 0) ? 0.0f : vmax0;
        warp_loss = softplus_g(2.0f * (2.5f - spos0))
                  + softplus_g(2.0f * (0.5f + s_neg0));
    }

    // consume row1 batch1
    consume_f4(b0, 4 * 32 + lane, lblf4_1, lblsub1, vmax1, spos1);
    consume_f4(b1, 5 * 32 + lane, lblf4_1, lblsub1, vmax1, spos1);
    consume_f4(b2, 6 * 32 + lane, lblf4_1, lblsub1, vmax1, spos1);
    consume_f4(b3, 7 * 32 + lane, lblf4_1, lblsub1, vmax1, spos1);

    // ---- row1 reduction + epilogue ----
    #pragma unroll
    for (int o = 16; o > 0; o >>= 1)
        vmax1 = fmaxf(vmax1, __shfl_xor_sync(0xffffffffu, vmax1, o));
    spos1 = __shfl_sync(0xffffffffu, spos1, lblf4_1 & 31);

    if (lane == 0) {
        const float s_neg1 = (lbl1 == 0) ? 0.0f : vmax1;
        warp_loss += softplus_g(2.0f * (2.5f - spos1))
                   + softplus_g(2.0f * (0.5f + s_neg1));
    }

    // Block reduction of per-warp (2-row) partial sums.
    __shared__ float s_part[WARPS_PER_BLOCK];
    if (lane == 0) s_part[warp] = warp_loss;
    __syncthreads();

    if (threadIdx.x == 0) {
        float blk = 0.0f;
        #pragma unroll
        for (int i = 0; i < WARPS_PER_BLOCK; ++i) blk += s_part[i];
        atomicAdd(&g_acc, (double)blk);
        __threadfence();
        const unsigned int ticket = atomicAdd(&g_done, 1u);
        if (ticket == gridDim.x - 1) {
            *out = (float)(g_acc / (double)NUM_B);
            g_acc = 0.0;
            g_done = 0;
        }
    }
}

extern "C" void kernel_launch(void* const* d_in, const int* in_sizes, int n_in,
                              void* d_out, int out_size)
{
    const float* scores = (const float*)d_in[0];
    const int*   labels = (const int*)d_in[1];
    float*       out    = (float*)d_out;

    const int grid = NUM_B / (2 * WARPS_PER_BLOCK);   // 4096
    ranking_loss_kernel<<<grid, WARPS_PER_BLOCK * 32>>>(scores, labels, out);
}

// round 13
// speedup vs baseline: 1.0468x; 1.0468x over previous
#include <cuda_runtime.h>
#include <cuda_bf16.h>
#include <math.h>

// RankingLoss: B=65536 rows, C=1024 classes, float32 scores, int32 labels.
// loss = mean_b [ log1p(exp(2*(2.5 - s_pos))) + log1p(exp(2*(0.5 + s_neg))) ]
//   s_pos = scores[b, label[b]]
//   s_neg = max_{c != label} scores[b,c]   (0 if label == 0)
//
// Converged configuration (best of 8 structural experiments):
//   - one warp per row, 32 lanes x 8 float4 = 1024 floats, coalesced LDG.128
//   - two explicit batches of 4 independent loads (MLP=4) with regs pinned
//     to 32 via __launch_bounds__(256, 8) -> 64 warps/SM resident
//   - one label-compare per float4; spos via single shfl from the statically
//     known owner lane (lblf4 & 31)
//   - double-precision atomic accumulation + last-block publish/reset
//     (graph-replay safe, deterministic)

#define NUM_B 65536
#define NUM_C 1024
#define WARPS_PER_BLOCK 8

__device__ double g_acc = 0.0;
__device__ unsigned int g_done = 0;

__device__ __forceinline__ float softplus_g(float t) {
    return (t > 20.0f) ? t : log1pf(__expf(t));
}

// Single compare per float4; label element selected by lblsub.
__device__ __forceinline__ void consume_f4(float4 v, int f4, int lblf4,
                                           int lblsub, float& vmax, float& spos) {
    float a0 = v.x, a1 = v.y, a2 = v.z, a3 = v.w;
    if (f4 == lblf4) {
        if (lblsub == 0) { spos = a0; a0 = -INFINITY; }
        else if (lblsub == 1) { spos = a1; a1 = -INFINITY; }
        else if (lblsub == 2) { spos = a2; a2 = -INFINITY; }
        else                  { spos = a3; a3 = -INFINITY; }
    }
    vmax = fmaxf(vmax, fmaxf(fmaxf(a0, a1), fmaxf(a2, a3)));
}

// minBlocksPerMultiprocessor=8 pins regs<=32 -> 64 warps/SM resident.
__global__ void __launch_bounds__(WARPS_PER_BLOCK * 32, 8)
ranking_loss_kernel(const float* __restrict__ scores,
                    const int* __restrict__ labels,
                    float* __restrict__ out)
{
    const int lane = threadIdx.x & 31;
    const int warp = threadIdx.x >> 5;
    const int row  = blockIdx.x * WARPS_PER_BLOCK + warp;

    const int lbl    = labels[row];
    const int lblf4  = lbl >> 2;
    const int lblsub = lbl & 3;

    const float4* __restrict__ rp =
        (const float4*)(scores + (size_t)row * NUM_C);

    float vmax = -INFINITY;
    float spos = -INFINITY;

    // Two explicit batches of 4 independent LDG.128 (MLP=4, regs held at 32).
    {
        float4 v0 = rp[0 * 32 + lane];
        float4 v1 = rp[1 * 32 + lane];
        float4 v2 = rp[2 * 32 + lane];
        float4 v3 = rp[3 * 32 + lane];
        consume_f4(v0, 0 * 32 + lane, lblf4, lblsub, vmax, spos);
        consume_f4(v1, 1 * 32 + lane, lblf4, lblsub, vmax, spos);
        consume_f4(v2, 2 * 32 + lane, lblf4, lblsub, vmax, spos);
        consume_f4(v3, 3 * 32 + lane, lblf4, lblsub, vmax, spos);
    }
    {
        float4 v0 = rp[4 * 32 + lane];
        float4 v1 = rp[5 * 32 + lane];
        float4 v2 = rp[6 * 32 + lane];
        float4 v3 = rp[7 * 32 + lane];
        consume_f4(v0, 4 * 32 + lane, lblf4, lblsub, vmax, spos);
        consume_f4(v1, 5 * 32 + lane, lblf4, lblsub, vmax, spos);
        consume_f4(v2, 6 * 32 + lane, lblf4, lblsub, vmax, spos);
        consume_f4(v3, 7 * 32 + lane, lblf4, lblsub, vmax, spos);
    }

    // vmax: 5-step warp tree. spos: one shfl from the statically known
    // owning lane (lane = lblf4 & 31, since f4 = w*32 + lane).
    #pragma unroll
    for (int o = 16; o > 0; o >>= 1)
        vmax = fmaxf(vmax, __shfl_xor_sync(0xffffffffu, vmax, o));
    spos = __shfl_sync(0xffffffffu, spos, lblf4 & 31);

    float row_loss = 0.0f;
    if (lane == 0) {
        const float s_neg = (lbl == 0) ? 0.0f : vmax;
        row_loss = softplus_g(2.0f * (2.5f - spos))
                 + softplus_g(2.0f * (0.5f + s_neg));
    }

    __shared__ float s_part[WARPS_PER_BLOCK];
    if (lane == 0) s_part[warp] = row_loss;
    __syncthreads();

    if (threadIdx.x == 0) {
        float blk = 0.0f;
        #pragma unroll
        for (int i = 0; i < WARPS_PER_BLOCK; ++i) blk += s_part[i];
        atomicAdd(&g_acc, (double)blk);
        __threadfence();
        const unsigned int ticket = atomicAdd(&g_done, 1u);
        if (ticket == gridDim.x - 1) {
            *out = (float)(g_acc / (double)NUM_B);
            g_acc = 0.0;
            g_done = 0;
        }
    }
}

extern "C" void kernel_launch(void* const* d_in, const int* in_sizes, int n_in,
                              void* d_out, int out_size)
{
    const float* scores = (const float*)d_in[0];
    const int*   labels = (const int*)d_in[1];
    float*       out    = (float*)d_out;

    const int grid = NUM_B / WARPS_PER_BLOCK;   // 8192
    ranking_loss_kernel<<<grid, WARPS_PER_BLOCK * 32>>>(scores, labels, out);
}